// round 10
// baseline (speedup 1.0000x reference)
#include <cuda_runtime.h>
#include <cuda_bf16.h>
#include <math.h>

#define N_NODES 20000
#define N_EDGES 640000
#define FEAT    128
#define NRBF    20
#define PI_F    3.14159265358979f
#define CUTOFF  5.0f
#define CHUNK   32

#define SCATTER_BLOCKS (N_EDGES / 128)          // 5000
#define GEMM_BLOCKS    (N_NODES / 16)           // 1250

typedef unsigned long long ull;

// ---------------- f32x2 packed-math helpers (Blackwell FFMA2 path) -----------
__device__ __forceinline__ ull pack2(float lo, float hi) {
    ull r; asm("mov.b64 %0, {%1, %2};" : "=l"(r) : "f"(lo), "f"(hi)); return r;
}
__device__ __forceinline__ void unpack2(ull v, float& lo, float& hi) {
    asm("mov.b64 {%0, %1}, %2;" : "=f"(lo), "=f"(hi) : "l"(v));
}
__device__ __forceinline__ ull fma2(ull a, ull b, ull c) {
    ull d; asm("fma.rn.f32x2 %0, %1, %2, %3;" : "=l"(d) : "l"(a), "l"(b), "l"(c)); return d;
}
__device__ __forceinline__ ull mul2(ull a, ull b) {
    ull d; asm("mul.rn.f32x2 %0, %1, %2;" : "=l"(d) : "l"(a), "l"(b)); return d;
}
__device__ __forceinline__ ull add2(ull a, ull b) {
    ull d; asm("add.rn.f32x2 %0, %1, %2;" : "=l"(d) : "l"(a), "l"(b)); return d;
}

// ---------------- scratch (static device allocations; no cudaMalloc) ----------
// g_count is zero at module load and re-zeroed by scan_kernel after each use,
// so the graph-replay invariant holds without a zeroing kernel.
__device__ int   g_count[N_NODES];
__device__ int   g_off[N_NODES + 1];
__device__ int   g_cursor[N_NODES];
__device__ int   g_perm[N_EDGES];
__device__ float g_phi[N_NODES * 3 * FEAT];    // 30.72 MB

// ---------------- launch 1: histogram by destination node ---------------------
// nbrs is int32 [N_EDGES, 2]: nbrs[2e] = dest node i, nbrs[2e+1] = src node j
__global__ void hist_kernel(const int* __restrict__ nbrs) {
    int e = blockIdx.x * blockDim.x + threadIdx.x;
    if (e < N_EDGES) {
        int i = nbrs[2 * e];
        atomicAdd(&g_count[i], 1);
    }
}

// ---------------- launch 2: single-block scan (+ self-clean of g_count) ------
__global__ void scan_kernel() {
    const int STRIP = 20;
    int t = threadIdx.x;
    int base = t * STRIP;
    int local[STRIP];
    int s = 0;
    #pragma unroll
    for (int u = 0; u < STRIP; ++u) {
        int idx = base + u;
        int c = 0;
        if (idx < N_NODES) { c = g_count[idx]; g_count[idx] = 0; }  // read + clean
        local[u] = s;
        s += c;
    }
    __shared__ int sums[1024];
    sums[t] = s;
    __syncthreads();
    for (int off = 1; off < 1024; off <<= 1) {
        int v = (t >= off) ? sums[t - off] : 0;
        __syncthreads();
        sums[t] += v;
        __syncthreads();
    }
    int pre = (t > 0) ? sums[t - 1] : 0;
    #pragma unroll
    for (int u = 0; u < STRIP; ++u) {
        int idx = base + u;
        if (idx < N_NODES) {
            int o = pre + local[u];
            g_off[idx]    = o;
            g_cursor[idx] = o;
        }
    }
    if (t == 1023) g_off[N_NODES] = sums[1023];
}

// ---------------- launch 3: fused scatter + node-feature MLP ------------------
__global__ __launch_bounds__(128, 4)
void scatter_gemm_kernel(const int* __restrict__ nbrs,
                         const float* __restrict__ S,
                         const float* __restrict__ W1, const float* __restrict__ b1,
                         const float* __restrict__ W2, const float* __restrict__ b2) {
    if (blockIdx.x < SCATTER_BLOCKS) {
        int e = blockIdx.x * 128 + threadIdx.x;
        int i = nbrs[2 * e];
        int pos = atomicAdd(&g_cursor[i], 1);
        g_perm[pos] = e;
        return;
    }

    __shared__ float As[16][FEAT];
    __shared__ float Hs[16][FEAT];
    int row0 = (blockIdx.x - SCATTER_BLOCKS) * 16;
    int tid = threadIdx.x;
    #pragma unroll
    for (int r = 0; r < 16; ++r)
        As[r][tid] = S[(size_t)(row0 + r) * FEAT + tid];
    __syncthreads();

    {
        float acc[16];
        #pragma unroll
        for (int r = 0; r < 16; ++r) acc[r] = 0.f;
        #pragma unroll 4
        for (int k = 0; k < FEAT; ++k) {
            float b = W1[k * FEAT + tid];
            #pragma unroll
            for (int r = 0; r < 16; ++r) acc[r] = fmaf(As[r][k], b, acc[r]);
        }
        float bias = b1[tid];
        #pragma unroll
        for (int r = 0; r < 16; ++r) {
            float x = acc[r] + bias;
            Hs[r][tid] = x / (1.f + expf(-x));   // silu
        }
    }
    __syncthreads();

    float a0[16], a1[16], a2[16];
    #pragma unroll
    for (int r = 0; r < 16; ++r) { a0[r] = 0.f; a1[r] = 0.f; a2[r] = 0.f; }

    #pragma unroll 2
    for (int k = 0; k < FEAT; ++k) {
        const float* wrow = W2 + (size_t)k * 384;
        float b0 = wrow[tid];
        float b1v = wrow[128 + tid];
        float b2v = wrow[256 + tid];
        #pragma unroll
        for (int r = 0; r < 16; ++r) {
            float h = Hs[r][k];
            a0[r] = fmaf(h, b0, a0[r]);
            a1[r] = fmaf(h, b1v, a1[r]);
            a2[r] = fmaf(h, b2v, a2[r]);
        }
    }
    float bb0 = b2[tid], bb1 = b2[128 + tid], bb2 = b2[256 + tid];
    #pragma unroll
    for (int r = 0; r < 16; ++r) {
        float* prow = g_phi + (size_t)(row0 + r) * 384;
        prow[tid]       = a0[r] + bb0;
        prow[128 + tid] = a1[r] + bb1;
        prow[256 + tid] = a2[r] + bb2;
    }
}

// ---------------- launch 4 (ncu-sampled slot): per-node message + aggregation -
// One CTA (192 threads = 3 groups of 64) per destination node i.
// Group g owns split g only -> per-thread Wd slice is 21 ull (42 regs).
//   group 0: i0 = phi0*ws0,  accumulates  sum_e i0 * v_j[e]     (needs v)
//   group 1: accumulates     sum_e phi1*ws1  (delta_s)
//   group 2: i2 = phi2*ws2,  accumulates  sum_e i2 * unit[e]    (needs u)
// delta_v = group0's sum + group2's sum (additive split), combined via smem.
__global__ __launch_bounds__(192, 4)
void node_kernel(const int* __restrict__ nbrs,
                 const float* __restrict__ r_ij,
                 const float* __restrict__ v_j,
                 const float* __restrict__ Wd,
                 const float* __restrict__ bd,
                 float* __restrict__ out) {
    int i   = blockIdx.x;
    int tid = threadIdx.x;          // 0..191
    int gid = tid >> 6;             // split group 0/1/2
    int wt  = tid & 63;             // lane within group
    int f2  = 2 * wt;               // feature pair
    int start = g_off[i];
    int end   = g_off[i + 1];

    // this group's Wd column-pairs; slot 20 = bd (env is the 21st rbf)
    ull wdg[NRBF + 1];
    #pragma unroll
    for (int k = 0; k < NRBF; ++k)
        wdg[k] = *(const ull*)(Wd + (size_t)k * 384 + gid * 128 + f2);
    wdg[NRBF] = *(const ull*)(bd + gid * 128 + f2);

    ull a0 = 0ull, a1 = 0ull, a2 = 0ull;   // group-specific accumulators

    __shared__ ull s_rbf2[NRBF + 1][CHUNK];  // [k][t]; [20][t] = env dup
    __shared__ ull s_u[CHUNK][3];            // unit vector, duplicated pairs
    __shared__ int s_j[CHUNK];
    __shared__ ull s_comb[64][3];            // group0 -> group2 combine

    for (int base = start; base < end; base += CHUNK) {
        int n = min(CHUNK, end - base);
        __syncthreads();  // protect smem from previous iteration's readers

        if (tid < n) {    // staged by (part of) group 0
            int e = g_perm[base + tid];
            s_j[tid] = nbrs[2 * e + 1];
            const float* rp = r_ij + 3 * (size_t)e;
            float x = rp[0], y = rp[1], z = rp[2];
            float d = sqrtf(fmaf(x, x, fmaf(y, y, fmaf(z, z, 3e-15f))));
            float invd = 1.f / d;
            s_u[tid][0] = pack2(x * invd, x * invd);
            s_u[tid][1] = pack2(y * invd, y * invd);
            s_u[tid][2] = pack2(z * invd, z * invd);
            // fast sincos; envelope reuses cos; rbf via Chebyshev recurrence.
            // Contributing edges have theta < pi (MUFU-accurate); d>=CUTOFF zeroed by env.
            float theta = d * (PI_F / CUTOFF);
            float st, ct;
            __sincosf(theta, &st, &ct);
            float env = (d < CUTOFF) ? 0.5f * (ct + 1.f) : 0.f;
            s_rbf2[NRBF][tid] = pack2(env, env);
            float sc = env * invd;
            float c2  = 2.f * ct;
            float skm = 0.f;
            float sk  = st;
            #pragma unroll
            for (int k = 0; k < NRBF; ++k) {
                float r = sk * sc;
                s_rbf2[k][tid] = pack2(r, r);
                float nx = fmaf(c2, sk, -skm);
                skm = sk; sk = nx;
            }
        }
        __syncthreads();

        if (gid == 0) {
            // preload edge 0
            int j = s_j[0];
            ull pn = *(const ull*)(g_phi + (size_t)j * 384 + f2);
            const float2* vr = (const float2*)(v_j + (size_t)j * 384 + 3 * (size_t)f2);
            float2 van = vr[0], vbn = vr[1], vcn = vr[2];
            for (int t = 0; t < n; ++t) {
                ull p = pn; float2 va = van, vb = vbn, vc = vcn;
                if (t + 1 < n) {
                    int jn = s_j[t + 1];
                    pn = *(const ull*)(g_phi + (size_t)jn * 384 + f2);
                    const float2* vrn = (const float2*)(v_j + (size_t)jn * 384 + 3 * (size_t)f2);
                    van = vrn[0]; vbn = vrn[1]; vcn = vrn[2];
                }
                ull ws = 0ull;
                #pragma unroll
                for (int k = 0; k <= NRBF; ++k)
                    ws = fma2(s_rbf2[k][t], wdg[k], ws);
                ull i0 = mul2(p, ws);
                a0 = fma2(i0, pack2(va.x, vb.y), a0);
                a1 = fma2(i0, pack2(va.y, vc.x), a1);
                a2 = fma2(i0, pack2(vb.x, vc.y), a2);
            }
        } else if (gid == 1) {
            int j = s_j[0];
            ull pn = *(const ull*)(g_phi + (size_t)j * 384 + 128 + f2);
            for (int t = 0; t < n; ++t) {
                ull p = pn;
                if (t + 1 < n)
                    pn = *(const ull*)(g_phi + (size_t)s_j[t + 1] * 384 + 128 + f2);
                ull ws = 0ull;
                #pragma unroll
                for (int k = 0; k <= NRBF; ++k)
                    ws = fma2(s_rbf2[k][t], wdg[k], ws);
                a0 = fma2(p, ws, a0);
            }
        } else {
            int j = s_j[0];
            ull pn = *(const ull*)(g_phi + (size_t)j * 384 + 256 + f2);
            for (int t = 0; t < n; ++t) {
                ull p = pn;
                if (t + 1 < n)
                    pn = *(const ull*)(g_phi + (size_t)s_j[t + 1] * 384 + 256 + f2);
                ull ws = 0ull;
                #pragma unroll
                for (int k = 0; k <= NRBF; ++k)
                    ws = fma2(s_rbf2[k][t], wdg[k], ws);
                ull i2 = mul2(p, ws);
                a0 = fma2(i2, s_u[t][0], a0);
                a1 = fma2(i2, s_u[t][1], a1);
                a2 = fma2(i2, s_u[t][2], a2);
            }
        }
    }

    // ---- combine & write outputs ----
    __syncthreads();
    if (gid == 0) {
        s_comb[wt][0] = a0;
        s_comb[wt][1] = a1;
        s_comb[wt][2] = a2;
    }
    __syncthreads();

    if (gid == 1) {
        float slo, shi;
        unpack2(a0, slo, shi);
        out[(size_t)i * FEAT + f2]     = slo;
        out[(size_t)i * FEAT + f2 + 1] = shi;
    } else if (gid == 2) {
        ull av0 = add2(a0, s_comb[wt][0]);
        ull av1 = add2(a1, s_comb[wt][1]);
        ull av2 = add2(a2, s_comb[wt][2]);
        float a0l, a0h, a1l, a1h, a2l, a2h;
        unpack2(av0, a0l, a0h);
        unpack2(av1, a1l, a1h);
        unpack2(av2, a2l, a2h);
        float* vout = out + (size_t)N_NODES * FEAT + ((size_t)i * FEAT + f2) * 3;
        vout[0] = a0l; vout[1] = a1l; vout[2] = a2l;
        vout[3] = a0h; vout[4] = a1h; vout[5] = a2h;
    }
}

// ---------------- launch ------------------------------------------------------
extern "C" void kernel_launch(void* const* d_in, const int* in_sizes, int n_in,
                              void* d_out, int out_size) {
    const float* s_j  = (const float*)d_in[0];
    const float* v_j  = (const float*)d_in[1];
    const float* r_ij = (const float*)d_in[2];
    const int*   nbrs = (const int*)d_in[3];     // int32 (JAX x64 disabled)
    const float* W1   = (const float*)d_in[4];
    const float* b1   = (const float*)d_in[5];
    const float* W2   = (const float*)d_in[6];
    const float* b2   = (const float*)d_in[7];
    const float* Wd   = (const float*)d_in[8];
    const float* bd   = (const float*)d_in[9];
    float* out = (float*)d_out;

    hist_kernel<<<N_EDGES / 256, 256>>>(nbrs);                       // launch 1
    scan_kernel<<<1, 1024>>>();                                      // launch 2
    scatter_gemm_kernel<<<SCATTER_BLOCKS + GEMM_BLOCKS, 128>>>(      // launch 3
        nbrs, s_j, W1, b1, W2, b2);
    node_kernel<<<N_NODES, 192>>>(nbrs, r_ij, v_j, Wd, bd, out);     // launch 4
}